// round 6
// baseline (speedup 1.0000x reference)
#include <cuda_runtime.h>
#include <cuda_bf16.h>

#define N_NODES 100000
#define N_EDGES 1600000
#define IN_CH   128
#define NG      16

typedef unsigned long long ull;

// ---------------- scratch (device globals) ----------------------------------
__device__ float g_y  [N_NODES * 64];   // x @ W_l^T
__device__ float g_xr [N_NODES * 64];   // x @ W_r^T
__device__ float g_agg[N_NODES * 64];   // segment_sum of y over dst
__device__ float g_deg[N_NODES];
__device__ float g_gsum[NG * 64];
__device__ float g_gcnt[NG];

// ---------------- zero kernels (slots 1-3) -----------------------------------
__global__ void zero_agg_lo() {
    int i = blockIdx.x * blockDim.x + threadIdx.x;
    int stride = gridDim.x * blockDim.x;
    float4 z4 = make_float4(0.f, 0.f, 0.f, 0.f);
    float4* a4 = reinterpret_cast<float4*>(g_agg);
    for (int j = i; j < N_NODES * 8; j += stride) a4[j] = z4;
}
__global__ void zero_agg_hi() {
    int i = blockIdx.x * blockDim.x + threadIdx.x;
    int stride = gridDim.x * blockDim.x;
    float4 z4 = make_float4(0.f, 0.f, 0.f, 0.f);
    float4* a4 = reinterpret_cast<float4*>(g_agg) + N_NODES * 8;
    for (int j = i; j < N_NODES * 8; j += stride) a4[j] = z4;
    for (int j = i; j < N_NODES; j += stride) g_deg[j] = 0.f;
}
__global__ void zero_small() {
    int i = threadIdx.x;
    if (i < NG * 64) g_gsum[i] = 0.f;
    if (i < NG) g_gcnt[i] = 0.f;
}

// ---------------- kernel (slot 4): fused node GEMM, f32x2 packed FMA ---------
// [y | xr] = x @ [W_l ; W_r]^T. 64 nodes x 128 outs / block, 256 thr.
// Micro-tile 4 rows x 8 cols per thread; cols paired into f32x2.
#define GEMM_BM 64
__global__ void node_gemm(const float* __restrict__ x,
                          const float* __restrict__ Wl,
                          const float* __restrict__ Wr) {
    extern __shared__ float smem[];
    float* Ws = smem;              // [128][128]  Ws[k][j] = Wcat[j][k]
    float* Xs = smem + 128 * 128;  // [64][132]

    int tid = threadIdx.x;
    for (int idx = tid; idx < 128 * 128; idx += 256) {
        int j = idx >> 7, k = idx & 127;
        float v = (j < 64) ? Wl[j * 128 + k] : Wr[(j - 64) * 128 + k];
        Ws[k * 128 + j] = v;
    }
    int nodeBase = blockIdx.x * GEMM_BM;
    for (int idx = tid; idx < GEMM_BM * 128; idx += 256) {
        int r = idx >> 7, k = idx & 127;
        int n = nodeBase + r;
        Xs[r * 132 + k] = (n < N_NODES) ? x[(size_t)n * 128 + k] : 0.f;
    }
    __syncthreads();

    int ty = tid >> 4, tx = tid & 15;

    ull acc[4][4];   // acc[r][c] = packed f32x2 for cols (tx*8+2c, tx*8+2c+1)
#pragma unroll
    for (int r = 0; r < 4; r++)
#pragma unroll
        for (int c = 0; c < 4; c++) acc[r][c] = 0ull;

#pragma unroll 4
    for (int k = 0; k < 128; k++) {
        // pack x values (row-broadcast) into f32x2
        ull xd[4];
#pragma unroll
        for (int r = 0; r < 4; r++) {
            float xv = Xs[(ty * 4 + r) * 132 + k];
            asm("mov.b64 %0, {%1, %1};" : "=l"(xd[r]) : "f"(xv));
        }
        // weight pairs: contiguous, read as packed 64-bit (2x 128-bit LDS)
        const ull* wrow = reinterpret_cast<const ull*>(&Ws[k * 128 + tx * 8]);
        ulonglong2 wa = *reinterpret_cast<const ulonglong2*>(wrow);
        ulonglong2 wb = *reinterpret_cast<const ulonglong2*>(wrow + 2);
        ull wv[4] = {wa.x, wa.y, wb.x, wb.y};
#pragma unroll
        for (int r = 0; r < 4; r++) {
#pragma unroll
            for (int c = 0; c < 4; c++) {
                asm("fma.rn.f32x2 %0, %1, %2, %3;"
                    : "=l"(acc[r][c]) : "l"(xd[r]), "l"(wv[c]), "l"(acc[r][c]));
            }
        }
    }

    int j = tx * 8;
#pragma unroll
    for (int r = 0; r < 4; r++) {
        int n = nodeBase + ty * 4 + r;
        if (n >= N_NODES) continue;
        ulonglong2 o0; o0.x = acc[r][0]; o0.y = acc[r][1];
        ulonglong2 o1; o1.x = acc[r][2]; o1.y = acc[r][3];
        if (j < 64) {
            *reinterpret_cast<ulonglong2*>(&g_y[(size_t)n * 64 + j])     = o0;
            *reinterpret_cast<ulonglong2*>(&g_y[(size_t)n * 64 + j + 4]) = o1;
        } else {
            *reinterpret_cast<ulonglong2*>(&g_xr[(size_t)n * 64 + j - 64])     = o0;
            *reinterpret_cast<ulonglong2*>(&g_xr[(size_t)n * 64 + j - 64 + 4]) = o1;
        }
    }
}

// ---------------- kernel (slot 5): edge scatter (push, f32 v4 reds) ----------
__global__ void edge_scatter(const int* __restrict__ ei) {
    int tid = threadIdx.x;
    int e = blockIdx.x * 16 + (tid >> 4);
    int t = tid & 15;
    if (e >= N_EDGES) return;
    int src = __ldg(&ei[e]);
    int dst = __ldg(&ei[N_EDGES + e]);

    const float4* ysrc = reinterpret_cast<const float4*>(g_y + (size_t)src * 64);
    float4 v = __ldg(ysrc + t);
    float* dptr = g_agg + (size_t)dst * 64 + t * 4;
    asm volatile("red.global.add.v4.f32 [%0], {%1, %2, %3, %4};"
                 :: "l"(dptr), "f"(v.x), "f"(v.y), "f"(v.z), "f"(v.w)
                 : "memory");
    if (t == 0) {
        float* dp = g_deg + dst;
        asm volatile("red.global.add.f32 [%0], %1;" :: "l"(dp), "f"(1.0f) : "memory");
    }
}

// ---------------- kernel (slot 6): combine + per-graph pool ------------------
#define POOL_BLOCKS 592
#define POOL_WARPS  (POOL_BLOCKS * 8)
#define POOL_CHUNK  ((N_NODES + POOL_WARPS - 1) / POOL_WARPS)
__global__ void combine_pool(const float* __restrict__ bl,
                             const int* __restrict__ batch) {
    int wid = (blockIdx.x * blockDim.x + threadIdx.x) >> 5;
    int lane = threadIdx.x & 31;
    int start = wid * POOL_CHUNK;
    if (start >= N_NODES) return;
    int end = min(start + POOL_CHUNK, N_NODES);

    float bl0 = bl[lane], bl1 = bl[lane + 32];
    float acc0 = 0.f, acc1 = 0.f, cnt = 0.f;
    int cur = batch[start];

    for (int n = start; n < end; n++) {
        int b = batch[n];
        if (b != cur) {
            atomicAdd(&g_gsum[cur * 64 + lane], acc0);
            atomicAdd(&g_gsum[cur * 64 + lane + 32], acc1);
            if (lane == 0) atomicAdd(&g_gcnt[cur], cnt);
            acc0 = acc1 = cnt = 0.f;
            cur = b;
        }
        float inv = 1.0f / fmaxf(g_deg[n], 1.0f);
        size_t base = (size_t)n * 64;
        float h0 = fmaxf(fmaf(g_agg[base + lane],      inv, g_xr[base + lane]      + bl0), 0.f);
        float h1 = fmaxf(fmaf(g_agg[base + lane + 32], inv, g_xr[base + lane + 32] + bl1), 0.f);
        acc0 += h0; acc1 += h1; cnt += 1.f;
    }
    atomicAdd(&g_gsum[cur * 64 + lane], acc0);
    atomicAdd(&g_gsum[cur * 64 + lane + 32], acc1);
    if (lane == 0) atomicAdd(&g_gcnt[cur], cnt);
}

// ---------------- kernel (slot 7): final MLP ---------------------------------
__global__ void final_mlp(const float* __restrict__ pk, const float* __restrict__ ck,
                          const float* __restrict__ Wp, const float* __restrict__ bp,
                          const float* __restrict__ Wc, const float* __restrict__ bc,
                          const float* __restrict__ Wh1, const float* __restrict__ bh1,
                          const float* __restrict__ Wh2, const float* __restrict__ bh2,
                          float* __restrict__ out) {
    __shared__ float z[NG][128];
    int w = threadIdx.x >> 5;
    int lane = threadIdx.x & 31;

    float cnt = fmaxf(g_gcnt[w], 1.0f);
    z[w][lane]      = g_gsum[w * 64 + lane] / cnt;
    z[w][lane + 32] = g_gsum[w * 64 + lane + 32] / cnt;

    float s = bp[lane];
#pragma unroll
    for (int k = 0; k < 7; k++) s = fmaf(pk[w * 7 + k], Wp[lane * 7 + k], s);
    z[w][64 + lane] = fmaxf(s, 0.f);

    s = bc[lane];
#pragma unroll
    for (int k = 0; k < 4; k++) s = fmaf(ck[w * 4 + k], Wc[lane * 4 + k], s);
    z[w][96 + lane] = fmaxf(s, 0.f);
    __syncwarp();

    float a0 = bh1[lane], a1 = bh1[lane + 32];
#pragma unroll 4
    for (int k = 0; k < 128; k++) {
        float zv = z[w][k];
        a0 = fmaf(zv, Wh1[lane * 128 + k], a0);
        a1 = fmaf(zv, Wh1[(lane + 32) * 128 + k], a1);
    }
    a0 = fmaxf(a0, 0.f);
    a1 = fmaxf(a1, 0.f);
    float r = a0 * Wh2[lane] + a1 * Wh2[lane + 32];
#pragma unroll
    for (int off = 16; off > 0; off >>= 1) r += __shfl_down_sync(0xffffffffu, r, off);
    if (lane == 0) out[w] = r + bh2[0];
}

// ---------------- launch -----------------------------------------------------
extern "C" void kernel_launch(void* const* d_in, const int* in_sizes, int n_in,
                              void* d_out, int out_size) {
    const float* x    = (const float*)d_in[0];
    const float* pk   = (const float*)d_in[1];
    const float* ck   = (const float*)d_in[2];
    const float* Wl   = (const float*)d_in[3];
    const float* bl   = (const float*)d_in[4];
    const float* Wr   = (const float*)d_in[5];
    const float* Wp   = (const float*)d_in[6];
    const float* bp   = (const float*)d_in[7];
    const float* Wc   = (const float*)d_in[8];
    const float* bc   = (const float*)d_in[9];
    const float* Wh1  = (const float*)d_in[10];
    const float* bh1  = (const float*)d_in[11];
    const float* Wh2  = (const float*)d_in[12];
    const float* bh2  = (const float*)d_in[13];
    const int*   ei   = (const int*)d_in[14];
    const int*   batch= (const int*)d_in[15];
    float* out = (float*)d_out;

    // slots 1-3: zeroing (arranged so node_gemm lands in profiled slot 4)
    zero_agg_lo<<<1024, 256>>>();
    zero_agg_hi<<<1024, 256>>>();
    zero_small<<<1, 1024>>>();

    // slot 4: node GEMM  <-- profiled
    int gemm_smem = (128 * 128 + GEMM_BM * 132) * (int)sizeof(float);
    cudaFuncSetAttribute(node_gemm, cudaFuncAttributeMaxDynamicSharedMemorySize, gemm_smem);
    node_gemm<<<(N_NODES + GEMM_BM - 1) / GEMM_BM, 256, gemm_smem>>>(x, Wl, Wr);

    // slot 5: edge scatter
    edge_scatter<<<(N_EDGES + 15) / 16, 256>>>(ei);

    // slot 6: combine + pool
    combine_pool<<<POOL_BLOCKS, 256>>>(bl, batch);

    // slot 7: final MLP
    final_mlp<<<1, 512>>>(pk, ck, Wp, bp, Wc, bc, Wh1, bh1, Wh2, bh2, out);

    (void)in_sizes; (void)n_in; (void)out_size;
}

// round 7
// speedup vs baseline: 1.1591x; 1.1591x over previous
#include <cuda_runtime.h>
#include <cuda_bf16.h>

#define N_NODES 100000
#define N_EDGES 1600000
#define IN_CH   128
#define NG      16

typedef unsigned long long ull;

// ---------------- scratch (device globals) ----------------------------------
__device__ float g_y  [N_NODES * 64];   // x @ W_l^T
__device__ float g_xr [N_NODES * 64];   // x @ W_r^T
__device__ float g_agg[N_NODES * 64];   // segment_sum of y over dst
__device__ float g_deg[N_NODES];
__device__ float g_gsum[NG * 64];
__device__ float g_gcnt[NG];

// ---------------- zero kernels (slots 1-3) -----------------------------------
__global__ void zero_agg_lo() {
    int i = blockIdx.x * blockDim.x + threadIdx.x;
    int stride = gridDim.x * blockDim.x;
    float4 z4 = make_float4(0.f, 0.f, 0.f, 0.f);
    float4* a4 = reinterpret_cast<float4*>(g_agg);
    for (int j = i; j < N_NODES * 8; j += stride) a4[j] = z4;
}
__global__ void zero_agg_hi() {
    int i = blockIdx.x * blockDim.x + threadIdx.x;
    int stride = gridDim.x * blockDim.x;
    float4 z4 = make_float4(0.f, 0.f, 0.f, 0.f);
    float4* a4 = reinterpret_cast<float4*>(g_agg) + N_NODES * 8;
    for (int j = i; j < N_NODES * 8; j += stride) a4[j] = z4;
    for (int j = i; j < N_NODES; j += stride) g_deg[j] = 0.f;
}
__global__ void zero_small() {
    int i = threadIdx.x;
    if (i < NG * 64) g_gsum[i] = 0.f;
    if (i < NG) g_gcnt[i] = 0.f;
}

// ---------------- kernel (slot 4): node GEMM, 4x16 micro-tile, f32x2 ---------
// [y | xr] = x @ [W_l ; W_r]^T.
// Block: 128 threads, 64 nodes x 128 cols. Thread (ty,tx): rows ty*4..+3,
// cols {tx*4 + c*32 .. +3} for c=0..3 (interleaved -> conflict-free LDS.128).
#define GEMM_BM 64
__global__ void __launch_bounds__(128, 2) node_gemm(const float* __restrict__ x,
                          const float* __restrict__ Wl,
                          const float* __restrict__ Wr) {
    extern __shared__ float smem[];
    float* Ws = smem;              // [128][128]  Ws[k][j] = Wcat[j][k]
    float* Xs = smem + 128 * 128;  // [64][132]

    int tid = threadIdx.x;
    // load W transposed into shared
    for (int idx = tid; idx < 128 * 128; idx += 128) {
        int j = idx >> 7, k = idx & 127;
        float v = (j < 64) ? Wl[j * 128 + k] : Wr[(j - 64) * 128 + k];
        Ws[k * 128 + j] = v;
    }
    int nodeBase = blockIdx.x * GEMM_BM;
    for (int idx = tid; idx < GEMM_BM * 32; idx += 128) {
        int r = idx >> 5, kq = idx & 31;       // float4-granular fill
        int n = nodeBase + r;
        float4 v = (n < N_NODES)
            ? *reinterpret_cast<const float4*>(&x[(size_t)n * 128 + kq * 4])
            : make_float4(0.f, 0.f, 0.f, 0.f);
        *reinterpret_cast<float4*>(&Xs[r * 132 + kq * 4]) = v;
    }
    __syncthreads();

    int ty = tid >> 3;   // 0..15 : rows ty*4..+3
    int tx = tid & 7;    // 0..7  : col groups tx*4 + c*32

    ull acc[4][4][2];    // [row][cgroup][pair]
#pragma unroll
    for (int r = 0; r < 4; r++)
#pragma unroll
        for (int c = 0; c < 4; c++) { acc[r][c][0] = 0ull; acc[r][c][1] = 0ull; }

#pragma unroll 2
    for (int k4 = 0; k4 < 128; k4 += 4) {
        float4 xv[4];
#pragma unroll
        for (int r = 0; r < 4; r++)
            xv[r] = *reinterpret_cast<const float4*>(&Xs[(ty * 4 + r) * 132 + k4]);
#pragma unroll
        for (int kk = 0; kk < 4; kk++) {
            int k = k4 + kk;
            ulonglong2 wv[4];
#pragma unroll
            for (int c = 0; c < 4; c++)
                wv[c] = *reinterpret_cast<const ulonglong2*>(&Ws[k * 128 + tx * 4 + c * 32]);
            ull xd[4];
#pragma unroll
            for (int r = 0; r < 4; r++) {
                float xvk = (kk == 0) ? xv[r].x : (kk == 1) ? xv[r].y
                          : (kk == 2) ? xv[r].z : xv[r].w;
                asm("mov.b64 %0, {%1, %1};" : "=l"(xd[r]) : "f"(xvk));
            }
#pragma unroll
            for (int r = 0; r < 4; r++) {
#pragma unroll
                for (int c = 0; c < 4; c++) {
                    asm("fma.rn.f32x2 %0, %1, %2, %3;"
                        : "=l"(acc[r][c][0]) : "l"(xd[r]), "l"(wv[c].x), "l"(acc[r][c][0]));
                    asm("fma.rn.f32x2 %0, %1, %2, %3;"
                        : "=l"(acc[r][c][1]) : "l"(xd[r]), "l"(wv[c].y), "l"(acc[r][c][1]));
                }
            }
        }
    }

#pragma unroll
    for (int r = 0; r < 4; r++) {
        int n = nodeBase + ty * 4 + r;
        if (n >= N_NODES) continue;
#pragma unroll
        for (int c = 0; c < 4; c++) {
            int j = tx * 4 + c * 32;       // 0..127
            ulonglong2 o; o.x = acc[r][c][0]; o.y = acc[r][c][1];
            if (j < 64)
                *reinterpret_cast<ulonglong2*>(&g_y[(size_t)n * 64 + j]) = o;
            else
                *reinterpret_cast<ulonglong2*>(&g_xr[(size_t)n * 64 + (j - 64)]) = o;
        }
    }
}

// ---------------- kernel (slot 5): edge scatter (push, f32 v4 reds) ----------
__global__ void edge_scatter(const int* __restrict__ ei) {
    int tid = threadIdx.x;
    int e = blockIdx.x * 16 + (tid >> 4);
    int t = tid & 15;
    if (e >= N_EDGES) return;
    int src = __ldg(&ei[e]);
    int dst = __ldg(&ei[N_EDGES + e]);

    const float4* ysrc = reinterpret_cast<const float4*>(g_y + (size_t)src * 64);
    float4 v = __ldg(ysrc + t);
    float* dptr = g_agg + (size_t)dst * 64 + t * 4;
    asm volatile("red.global.add.v4.f32 [%0], {%1, %2, %3, %4};"
                 :: "l"(dptr), "f"(v.x), "f"(v.y), "f"(v.z), "f"(v.w)
                 : "memory");
    if (t == 0) {
        float* dp = g_deg + dst;
        asm volatile("red.global.add.f32 [%0], %1;" :: "l"(dp), "f"(1.0f) : "memory");
    }
}

// ---------------- kernel (slot 6): combine + per-graph pool ------------------
#define POOL_BLOCKS 592
#define POOL_WARPS  (POOL_BLOCKS * 8)
#define POOL_CHUNK  ((N_NODES + POOL_WARPS - 1) / POOL_WARPS)
__global__ void combine_pool(const float* __restrict__ bl,
                             const int* __restrict__ batch) {
    int wid = (blockIdx.x * blockDim.x + threadIdx.x) >> 5;
    int lane = threadIdx.x & 31;
    int start = wid * POOL_CHUNK;
    if (start >= N_NODES) return;
    int end = min(start + POOL_CHUNK, N_NODES);

    float bl0 = bl[lane], bl1 = bl[lane + 32];
    float acc0 = 0.f, acc1 = 0.f, cnt = 0.f;
    int cur = batch[start];

    for (int n = start; n < end; n++) {
        int b = batch[n];
        if (b != cur) {
            atomicAdd(&g_gsum[cur * 64 + lane], acc0);
            atomicAdd(&g_gsum[cur * 64 + lane + 32], acc1);
            if (lane == 0) atomicAdd(&g_gcnt[cur], cnt);
            acc0 = acc1 = cnt = 0.f;
            cur = b;
        }
        float inv = 1.0f / fmaxf(g_deg[n], 1.0f);
        size_t base = (size_t)n * 64;
        float h0 = fmaxf(fmaf(g_agg[base + lane],      inv, g_xr[base + lane]      + bl0), 0.f);
        float h1 = fmaxf(fmaf(g_agg[base + lane + 32], inv, g_xr[base + lane + 32] + bl1), 0.f);
        acc0 += h0; acc1 += h1; cnt += 1.f;
    }
    atomicAdd(&g_gsum[cur * 64 + lane], acc0);
    atomicAdd(&g_gsum[cur * 64 + lane + 32], acc1);
    if (lane == 0) atomicAdd(&g_gcnt[cur], cnt);
}

// ---------------- kernel (slot 7): final MLP ---------------------------------
__global__ void final_mlp(const float* __restrict__ pk, const float* __restrict__ ck,
                          const float* __restrict__ Wp, const float* __restrict__ bp,
                          const float* __restrict__ Wc, const float* __restrict__ bc,
                          const float* __restrict__ Wh1, const float* __restrict__ bh1,
                          const float* __restrict__ Wh2, const float* __restrict__ bh2,
                          float* __restrict__ out) {
    __shared__ float z[NG][128];
    int w = threadIdx.x >> 5;
    int lane = threadIdx.x & 31;

    float cnt = fmaxf(g_gcnt[w], 1.0f);
    z[w][lane]      = g_gsum[w * 64 + lane] / cnt;
    z[w][lane + 32] = g_gsum[w * 64 + lane + 32] / cnt;

    float s = bp[lane];
#pragma unroll
    for (int k = 0; k < 7; k++) s = fmaf(pk[w * 7 + k], Wp[lane * 7 + k], s);
    z[w][64 + lane] = fmaxf(s, 0.f);

    s = bc[lane];
#pragma unroll
    for (int k = 0; k < 4; k++) s = fmaf(ck[w * 4 + k], Wc[lane * 4 + k], s);
    z[w][96 + lane] = fmaxf(s, 0.f);
    __syncwarp();

    float a0 = bh1[lane], a1 = bh1[lane + 32];
#pragma unroll 4
    for (int k = 0; k < 128; k++) {
        float zv = z[w][k];
        a0 = fmaf(zv, Wh1[lane * 128 + k], a0);
        a1 = fmaf(zv, Wh1[(lane + 32) * 128 + k], a1);
    }
    a0 = fmaxf(a0, 0.f);
    a1 = fmaxf(a1, 0.f);
    float r = a0 * Wh2[lane] + a1 * Wh2[lane + 32];
#pragma unroll
    for (int off = 16; off > 0; off >>= 1) r += __shfl_down_sync(0xffffffffu, r, off);
    if (lane == 0) out[w] = r + bh2[0];
}

// ---------------- launch -----------------------------------------------------
extern "C" void kernel_launch(void* const* d_in, const int* in_sizes, int n_in,
                              void* d_out, int out_size) {
    const float* x    = (const float*)d_in[0];
    const float* pk   = (const float*)d_in[1];
    const float* ck   = (const float*)d_in[2];
    const float* Wl   = (const float*)d_in[3];
    const float* bl   = (const float*)d_in[4];
    const float* Wr   = (const float*)d_in[5];
    const float* Wp   = (const float*)d_in[6];
    const float* bp   = (const float*)d_in[7];
    const float* Wc   = (const float*)d_in[8];
    const float* bc   = (const float*)d_in[9];
    const float* Wh1  = (const float*)d_in[10];
    const float* bh1  = (const float*)d_in[11];
    const float* Wh2  = (const float*)d_in[12];
    const float* bh2  = (const float*)d_in[13];
    const int*   ei   = (const int*)d_in[14];
    const int*   batch= (const int*)d_in[15];
    float* out = (float*)d_out;

    // slots 1-3: zeroing (node_gemm stays in profiled slot 4)
    zero_agg_lo<<<1024, 256>>>();
    zero_agg_hi<<<1024, 256>>>();
    zero_small<<<1, 1024>>>();

    // slot 4: node GEMM  <-- profiled
    int gemm_smem = (128 * 128 + GEMM_BM * 132) * (int)sizeof(float);
    cudaFuncSetAttribute(node_gemm, cudaFuncAttributeMaxDynamicSharedMemorySize, gemm_smem);
    node_gemm<<<(N_NODES + GEMM_BM - 1) / GEMM_BM, 128, gemm_smem>>>(x, Wl, Wr);

    // slot 5: edge scatter
    edge_scatter<<<(N_EDGES + 15) / 16, 256>>>(ei);

    // slot 6: combine + pool
    combine_pool<<<POOL_BLOCKS, 256>>>(bl, batch);

    // slot 7: final MLP
    final_mlp<<<1, 512>>>(pk, ck, Wp, bp, Wc, bc, Wh1, bh1, Wh2, bh2, out);

    (void)in_sizes; (void)n_in; (void)out_size;
}

// round 8
// speedup vs baseline: 1.1726x; 1.0117x over previous
#include <cuda_runtime.h>
#include <cuda_bf16.h>

#define N_NODES 100000
#define N_EDGES 1600000
#define IN_CH   128
#define NG      16

typedef unsigned long long ull;

// ---------------- scratch (device globals) ----------------------------------
__device__ float g_y  [N_NODES * 64];   // x @ W_l^T
__device__ float g_xr [N_NODES * 64];   // x @ W_r^T
__device__ float g_agg[N_NODES * 64];   // segment_sum of y over dst
__device__ float g_deg[N_NODES];
__device__ float g_gsum[NG * 64];
__device__ float g_gcnt[NG];

// ---------------- zero kernels (slots 1-3) -----------------------------------
__global__ void zero_agg_lo() {
    int i = blockIdx.x * blockDim.x + threadIdx.x;
    int stride = gridDim.x * blockDim.x;
    float4 z4 = make_float4(0.f, 0.f, 0.f, 0.f);
    float4* a4 = reinterpret_cast<float4*>(g_agg);
    for (int j = i; j < N_NODES * 8; j += stride) a4[j] = z4;
}
__global__ void zero_agg_hi() {
    int i = blockIdx.x * blockDim.x + threadIdx.x;
    int stride = gridDim.x * blockDim.x;
    float4 z4 = make_float4(0.f, 0.f, 0.f, 0.f);
    float4* a4 = reinterpret_cast<float4*>(g_agg) + N_NODES * 8;
    for (int j = i; j < N_NODES * 8; j += stride) a4[j] = z4;
    for (int j = i; j < N_NODES; j += stride) g_deg[j] = 0.f;
}
__global__ void zero_small() {
    int i = threadIdx.x;
    if (i < NG * 64) g_gsum[i] = 0.f;
    if (i < NG) g_gcnt[i] = 0.f;
}

// ---------------- kernel (slot 4): node GEMM, k-major X tile, f32x2 ----------
// [y | xr] = x @ [W_l ; W_r]^T.
// Block: 128 threads, 64 nodes x 128 cols.
// X tile: Xs4[kq][row] (kq = k/4) -> per-k4 loads are 2-way (2 wf) instead of 8.
// W tile: Ws[k][j], thread cols {tx*4 + c*32} -> conflict-free LDS.128.
#define GEMM_BM 64
__global__ void __launch_bounds__(128, 2) node_gemm(const float* __restrict__ x,
                          const float* __restrict__ Wl,
                          const float* __restrict__ Wr) {
    extern __shared__ float smem[];
    float*  Ws  = smem;                                  // [128][128]
    float4* Xs4 = reinterpret_cast<float4*>(smem + 128 * 128);  // [32][64]

    int tid = threadIdx.x;
    // load W transposed into shared: Ws[k][j] = Wcat[j][k]
    for (int idx = tid; idx < 128 * 128; idx += 128) {
        int j = idx >> 7, k = idx & 127;
        float v = (j < 64) ? Wl[j * 128 + k] : Wr[(j - 64) * 128 + k];
        Ws[k * 128 + j] = v;
    }
    int nodeBase = blockIdx.x * GEMM_BM;
    // fill X tile k-major: Xs4[kq*64 + row] = x[row][kq*4..+3]
    // row = idx & 63 -> consecutive lanes write consecutive slots (no smem conflicts)
    for (int idx = tid; idx < GEMM_BM * 32; idx += 128) {
        int row = idx & 63, kq = idx >> 6;
        int n = nodeBase + row;
        float4 v = (n < N_NODES)
            ? *reinterpret_cast<const float4*>(&x[(size_t)n * 128 + kq * 4])
            : make_float4(0.f, 0.f, 0.f, 0.f);
        Xs4[kq * 64 + row] = v;
    }
    __syncthreads();

    int ty = tid >> 3;   // 0..15 : rows ty*4..+3
    int tx = tid & 7;    // 0..7  : col groups tx*4 + c*32

    ull acc[4][4][2];    // [row][cgroup][pair]
#pragma unroll
    for (int r = 0; r < 4; r++)
#pragma unroll
        for (int c = 0; c < 4; c++) { acc[r][c][0] = 0ull; acc[r][c][1] = 0ull; }

#pragma unroll 2
    for (int k4 = 0; k4 < 128; k4 += 4) {
        float4 xv[4];
#pragma unroll
        for (int r = 0; r < 4; r++)
            xv[r] = Xs4[(k4 >> 2) * 64 + ty * 4 + r];
#pragma unroll
        for (int kk = 0; kk < 4; kk++) {
            int k = k4 + kk;
            ulonglong2 wv[4];
#pragma unroll
            for (int c = 0; c < 4; c++)
                wv[c] = *reinterpret_cast<const ulonglong2*>(&Ws[k * 128 + tx * 4 + c * 32]);
            ull xd[4];
#pragma unroll
            for (int r = 0; r < 4; r++) {
                float xvk = (kk == 0) ? xv[r].x : (kk == 1) ? xv[r].y
                          : (kk == 2) ? xv[r].z : xv[r].w;
                asm("mov.b64 %0, {%1, %1};" : "=l"(xd[r]) : "f"(xvk));
            }
#pragma unroll
            for (int r = 0; r < 4; r++) {
#pragma unroll
                for (int c = 0; c < 4; c++) {
                    asm("fma.rn.f32x2 %0, %1, %2, %3;"
                        : "=l"(acc[r][c][0]) : "l"(xd[r]), "l"(wv[c].x), "l"(acc[r][c][0]));
                    asm("fma.rn.f32x2 %0, %1, %2, %3;"
                        : "=l"(acc[r][c][1]) : "l"(xd[r]), "l"(wv[c].y), "l"(acc[r][c][1]));
                }
            }
        }
    }

#pragma unroll
    for (int r = 0; r < 4; r++) {
        int n = nodeBase + ty * 4 + r;
        if (n >= N_NODES) continue;
#pragma unroll
        for (int c = 0; c < 4; c++) {
            int j = tx * 4 + c * 32;       // 0..127
            ulonglong2 o; o.x = acc[r][c][0]; o.y = acc[r][c][1];
            if (j < 64)
                *reinterpret_cast<ulonglong2*>(&g_y[(size_t)n * 64 + j]) = o;
            else
                *reinterpret_cast<ulonglong2*>(&g_xr[(size_t)n * 64 + (j - 64)]) = o;
        }
    }
}

// ---------------- kernel (slot 5): edge scatter (push, f32 v4 reds) ----------
__global__ void edge_scatter(const int* __restrict__ ei) {
    int tid = threadIdx.x;
    int e = blockIdx.x * 16 + (tid >> 4);
    int t = tid & 15;
    if (e >= N_EDGES) return;
    int src = __ldg(&ei[e]);
    int dst = __ldg(&ei[N_EDGES + e]);

    const float4* ysrc = reinterpret_cast<const float4*>(g_y + (size_t)src * 64);
    float4 v = __ldg(ysrc + t);
    float* dptr = g_agg + (size_t)dst * 64 + t * 4;
    asm volatile("red.global.add.v4.f32 [%0], {%1, %2, %3, %4};"
                 :: "l"(dptr), "f"(v.x), "f"(v.y), "f"(v.z), "f"(v.w)
                 : "memory");
    if (t == 0) {
        float* dp = g_deg + dst;
        asm volatile("red.global.add.f32 [%0], %1;" :: "l"(dp), "f"(1.0f) : "memory");
    }
}

// ---------------- kernel (slot 6): combine + per-graph pool ------------------
#define POOL_BLOCKS 592
#define POOL_WARPS  (POOL_BLOCKS * 8)
#define POOL_CHUNK  ((N_NODES + POOL_WARPS - 1) / POOL_WARPS)
__global__ void combine_pool(const float* __restrict__ bl,
                             const int* __restrict__ batch) {
    int wid = (blockIdx.x * blockDim.x + threadIdx.x) >> 5;
    int lane = threadIdx.x & 31;
    int start = wid * POOL_CHUNK;
    if (start >= N_NODES) return;
    int end = min(start + POOL_CHUNK, N_NODES);

    float bl0 = bl[lane], bl1 = bl[lane + 32];
    float acc0 = 0.f, acc1 = 0.f, cnt = 0.f;
    int cur = batch[start];

    for (int n = start; n < end; n++) {
        int b = batch[n];
        if (b != cur) {
            atomicAdd(&g_gsum[cur * 64 + lane], acc0);
            atomicAdd(&g_gsum[cur * 64 + lane + 32], acc1);
            if (lane == 0) atomicAdd(&g_gcnt[cur], cnt);
            acc0 = acc1 = cnt = 0.f;
            cur = b;
        }
        float inv = 1.0f / fmaxf(g_deg[n], 1.0f);
        size_t base = (size_t)n * 64;
        float h0 = fmaxf(fmaf(g_agg[base + lane],      inv, g_xr[base + lane]      + bl0), 0.f);
        float h1 = fmaxf(fmaf(g_agg[base + lane + 32], inv, g_xr[base + lane + 32] + bl1), 0.f);
        acc0 += h0; acc1 += h1; cnt += 1.f;
    }
    atomicAdd(&g_gsum[cur * 64 + lane], acc0);
    atomicAdd(&g_gsum[cur * 64 + lane + 32], acc1);
    if (lane == 0) atomicAdd(&g_gcnt[cur], cnt);
}

// ---------------- kernel (slot 7): final MLP ---------------------------------
__global__ void final_mlp(const float* __restrict__ pk, const float* __restrict__ ck,
                          const float* __restrict__ Wp, const float* __restrict__ bp,
                          const float* __restrict__ Wc, const float* __restrict__ bc,
                          const float* __restrict__ Wh1, const float* __restrict__ bh1,
                          const float* __restrict__ Wh2, const float* __restrict__ bh2,
                          float* __restrict__ out) {
    __shared__ float z[NG][128];
    int w = threadIdx.x >> 5;
    int lane = threadIdx.x & 31;

    float cnt = fmaxf(g_gcnt[w], 1.0f);
    z[w][lane]      = g_gsum[w * 64 + lane] / cnt;
    z[w][lane + 32] = g_gsum[w * 64 + lane + 32] / cnt;

    float s = bp[lane];
#pragma unroll
    for (int k = 0; k < 7; k++) s = fmaf(pk[w * 7 + k], Wp[lane * 7 + k], s);
    z[w][64 + lane] = fmaxf(s, 0.f);

    s = bc[lane];
#pragma unroll
    for (int k = 0; k < 4; k++) s = fmaf(ck[w * 4 + k], Wc[lane * 4 + k], s);
    z[w][96 + lane] = fmaxf(s, 0.f);
    __syncwarp();

    float a0 = bh1[lane], a1 = bh1[lane + 32];
#pragma unroll 4
    for (int k = 0; k < 128; k++) {
        float zv = z[w][k];
        a0 = fmaf(zv, Wh1[lane * 128 + k], a0);
        a1 = fmaf(zv, Wh1[(lane + 32) * 128 + k], a1);
    }
    a0 = fmaxf(a0, 0.f);
    a1 = fmaxf(a1, 0.f);
    float r = a0 * Wh2[lane] + a1 * Wh2[lane + 32];
#pragma unroll
    for (int off = 16; off > 0; off >>= 1) r += __shfl_down_sync(0xffffffffu, r, off);
    if (lane == 0) out[w] = r + bh2[0];
}

// ---------------- launch -----------------------------------------------------
extern "C" void kernel_launch(void* const* d_in, const int* in_sizes, int n_in,
                              void* d_out, int out_size) {
    const float* x    = (const float*)d_in[0];
    const float* pk   = (const float*)d_in[1];
    const float* ck   = (const float*)d_in[2];
    const float* Wl   = (const float*)d_in[3];
    const float* bl   = (const float*)d_in[4];
    const float* Wr   = (const float*)d_in[5];
    const float* Wp   = (const float*)d_in[6];
    const float* bp   = (const float*)d_in[7];
    const float* Wc   = (const float*)d_in[8];
    const float* bc   = (const float*)d_in[9];
    const float* Wh1  = (const float*)d_in[10];
    const float* bh1  = (const float*)d_in[11];
    const float* Wh2  = (const float*)d_in[12];
    const float* bh2  = (const float*)d_in[13];
    const int*   ei   = (const int*)d_in[14];
    const int*   batch= (const int*)d_in[15];
    float* out = (float*)d_out;

    // slots 1-3: zeroing (node_gemm stays in profiled slot 4)
    zero_agg_lo<<<1024, 256>>>();
    zero_agg_hi<<<1024, 256>>>();
    zero_small<<<1, 1024>>>();

    // slot 4: node GEMM  <-- profiled
    int gemm_smem = 128 * 128 * 4 + 32 * 64 * 16;   // 98304 bytes
    cudaFuncSetAttribute(node_gemm, cudaFuncAttributeMaxDynamicSharedMemorySize, gemm_smem);
    node_gemm<<<(N_NODES + GEMM_BM - 1) / GEMM_BM, 128, gemm_smem>>>(x, Wl, Wr);

    // slot 5: edge scatter
    edge_scatter<<<(N_EDGES + 15) / 16, 256>>>(ei);

    // slot 6: combine + pool
    combine_pool<<<POOL_BLOCKS, 256>>>(bl, batch);

    // slot 7: final MLP
    final_mlp<<<1, 512>>>(pk, ck, Wp, bp, Wc, bc, Wh1, bh1, Wh2, bh2, out);

    (void)in_sizes; (void)n_in; (void)out_size;
}

// round 9
// speedup vs baseline: 1.7829x; 1.5204x over previous
#include <cuda_runtime.h>
#include <cuda_bf16.h>

#define N_NODES 100000
#define N_EDGES 1600000
#define IN_CH   128
#define NG      16

typedef unsigned long long ull;

// ---------------- scratch (device globals) ----------------------------------
__device__ float g_y  [N_NODES * 64];   // x @ W_l^T
__device__ float g_xr [N_NODES * 64];   // x @ W_r^T
__device__ float g_agg[N_NODES * 64];   // segment_sum of y over dst
__device__ float g_deg[N_NODES];
__device__ float g_gsum[NG * 64];
__device__ float g_gcnt[NG];

// ---------------- zero kernels (slots 1-3) -----------------------------------
__global__ void zero_agg_lo() {
    int i = blockIdx.x * blockDim.x + threadIdx.x;
    int stride = gridDim.x * blockDim.x;
    float4 z4 = make_float4(0.f, 0.f, 0.f, 0.f);
    float4* a4 = reinterpret_cast<float4*>(g_agg);
    for (int j = i; j < N_NODES * 8; j += stride) a4[j] = z4;
}
__global__ void zero_agg_hi() {
    int i = blockIdx.x * blockDim.x + threadIdx.x;
    int stride = gridDim.x * blockDim.x;
    float4 z4 = make_float4(0.f, 0.f, 0.f, 0.f);
    float4* a4 = reinterpret_cast<float4*>(g_agg) + N_NODES * 8;
    for (int j = i; j < N_NODES * 8; j += stride) a4[j] = z4;
    for (int j = i; j < N_NODES; j += stride) g_deg[j] = 0.f;
}
__global__ void zero_small() {
    int i = threadIdx.x;
    if (i < NG * 64) g_gsum[i] = 0.f;
    if (i < NG) g_gcnt[i] = 0.f;
}

// ---------------- kernel (slot 4): node GEMM via tf32 mma.sync ---------------
// [y | xr] = x @ [W_l ; W_r]^T using m16n8k8 tf32 tensor-core MMA.
// Block: 256 thr (8 warps), 128 nodes x 128 cols. Warp w: nodes w*16..+15,
// all 128 cols. A fragments straight from gmem; B from padded smem (tf32 bits).
#define GEMM_BM 128
__device__ __forceinline__ unsigned f2tf32(float f) {
    unsigned u;
    asm("cvt.rna.tf32.f32 %0, %1;" : "=r"(u) : "f"(f));
    return u;
}
__global__ void __launch_bounds__(256, 2) node_gemm(const float* __restrict__ x,
                          const float* __restrict__ Wl,
                          const float* __restrict__ Wr) {
    extern __shared__ unsigned Wsm[];   // [128][132] tf32 bits; Wsm[n][k]

    int tid = threadIdx.x;
    // fill W tile (tf32-converted): Wsm[n][k] = tf32(Wcat[n][k])
    for (int idx = tid; idx < 128 * 128; idx += 256) {
        int n = idx >> 7, k = idx & 127;
        float v = (n < 64) ? Wl[n * 128 + k] : Wr[(n - 64) * 128 + k];
        Wsm[n * 132 + k] = f2tf32(v);
    }
    __syncthreads();

    int w    = tid >> 5;          // warp 0..7
    int lane = tid & 31;
    int gid  = lane >> 2;         // group 0..7
    int tig  = lane & 3;          // thread-in-group 0..3

    int nodeBase = blockIdx.x * GEMM_BM + w * 16;
    int r0 = nodeBase + gid;
    int r1 = r0 + 8;
    // clamp for the final partial block (stores are guarded)
    int r0c = min(r0, N_NODES - 1);
    int r1c = min(r1, N_NODES - 1);
    const float* xr0 = x + (size_t)r0c * 128;
    const float* xr1 = x + (size_t)r1c * 128;

    float acc[16][4];
#pragma unroll
    for (int nt = 0; nt < 16; nt++)
#pragma unroll
        for (int c = 0; c < 4; c++) acc[nt][c] = 0.f;

#pragma unroll
    for (int ks = 0; ks < 16; ks++) {
        int c0 = ks * 8 + tig;
        unsigned a0 = f2tf32(__ldg(xr0 + c0));
        unsigned a1 = f2tf32(__ldg(xr1 + c0));
        unsigned a2 = f2tf32(__ldg(xr0 + c0 + 4));
        unsigned a3 = f2tf32(__ldg(xr1 + c0 + 4));
#pragma unroll
        for (int nt = 0; nt < 16; nt++) {
            unsigned b0 = Wsm[(nt * 8 + gid) * 132 + ks * 8 + tig];
            unsigned b1 = Wsm[(nt * 8 + gid) * 132 + ks * 8 + tig + 4];
            asm("mma.sync.aligned.m16n8k8.row.col.f32.tf32.tf32.f32 "
                "{%0,%1,%2,%3}, {%4,%5,%6,%7}, {%8,%9}, {%0,%1,%2,%3};"
                : "+f"(acc[nt][0]), "+f"(acc[nt][1]), "+f"(acc[nt][2]), "+f"(acc[nt][3])
                : "r"(a0), "r"(a1), "r"(a2), "r"(a3), "r"(b0), "r"(b1));
        }
    }

    // epilogue: d(row, col): c0/c1 -> row gid, cols 2tig,2tig+1 ; c2/c3 -> row gid+8
#pragma unroll
    for (int nt = 0; nt < 16; nt++) {
        int j = nt * 8 + 2 * tig;          // 0..127, even
        float2 lo = make_float2(acc[nt][0], acc[nt][1]);
        float2 hi = make_float2(acc[nt][2], acc[nt][3]);
        if (r0 < N_NODES) {
            if (j < 64) *reinterpret_cast<float2*>(&g_y [(size_t)r0 * 64 + j]) = lo;
            else        *reinterpret_cast<float2*>(&g_xr[(size_t)r0 * 64 + j - 64]) = lo;
        }
        if (r1 < N_NODES) {
            if (j < 64) *reinterpret_cast<float2*>(&g_y [(size_t)r1 * 64 + j]) = hi;
            else        *reinterpret_cast<float2*>(&g_xr[(size_t)r1 * 64 + j - 64]) = hi;
        }
    }
}

// ---------------- kernel (slot 5): edge scatter (push, f32 v4 reds) ----------
__global__ void edge_scatter(const int* __restrict__ ei) {
    int tid = threadIdx.x;
    int e = blockIdx.x * 16 + (tid >> 4);
    int t = tid & 15;
    if (e >= N_EDGES) return;
    int src = __ldg(&ei[e]);
    int dst = __ldg(&ei[N_EDGES + e]);

    const float4* ysrc = reinterpret_cast<const float4*>(g_y + (size_t)src * 64);
    float4 v = __ldg(ysrc + t);
    float* dptr = g_agg + (size_t)dst * 64 + t * 4;
    asm volatile("red.global.add.v4.f32 [%0], {%1, %2, %3, %4};"
                 :: "l"(dptr), "f"(v.x), "f"(v.y), "f"(v.z), "f"(v.w)
                 : "memory");
    if (t == 0) {
        float* dp = g_deg + dst;
        asm volatile("red.global.add.f32 [%0], %1;" :: "l"(dp), "f"(1.0f) : "memory");
    }
}

// ---------------- kernel (slot 6): combine + per-graph pool ------------------
#define POOL_BLOCKS 592
#define POOL_WARPS  (POOL_BLOCKS * 8)
#define POOL_CHUNK  ((N_NODES + POOL_WARPS - 1) / POOL_WARPS)
__global__ void combine_pool(const float* __restrict__ bl,
                             const int* __restrict__ batch) {
    int wid = (blockIdx.x * blockDim.x + threadIdx.x) >> 5;
    int lane = threadIdx.x & 31;
    int start = wid * POOL_CHUNK;
    if (start >= N_NODES) return;
    int end = min(start + POOL_CHUNK, N_NODES);

    float bl0 = bl[lane], bl1 = bl[lane + 32];
    float acc0 = 0.f, acc1 = 0.f, cnt = 0.f;
    int cur = batch[start];

    for (int n = start; n < end; n++) {
        int b = batch[n];
        if (b != cur) {
            atomicAdd(&g_gsum[cur * 64 + lane], acc0);
            atomicAdd(&g_gsum[cur * 64 + lane + 32], acc1);
            if (lane == 0) atomicAdd(&g_gcnt[cur], cnt);
            acc0 = acc1 = cnt = 0.f;
            cur = b;
        }
        float inv = 1.0f / fmaxf(g_deg[n], 1.0f);
        size_t base = (size_t)n * 64;
        float h0 = fmaxf(fmaf(g_agg[base + lane],      inv, g_xr[base + lane]      + bl0), 0.f);
        float h1 = fmaxf(fmaf(g_agg[base + lane + 32], inv, g_xr[base + lane + 32] + bl1), 0.f);
        acc0 += h0; acc1 += h1; cnt += 1.f;
    }
    atomicAdd(&g_gsum[cur * 64 + lane], acc0);
    atomicAdd(&g_gsum[cur * 64 + lane + 32], acc1);
    if (lane == 0) atomicAdd(&g_gcnt[cur], cnt);
}

// ---------------- kernel (slot 7): final MLP ---------------------------------
__global__ void final_mlp(const float* __restrict__ pk, const float* __restrict__ ck,
                          const float* __restrict__ Wp, const float* __restrict__ bp,
                          const float* __restrict__ Wc, const float* __restrict__ bc,
                          const float* __restrict__ Wh1, const float* __restrict__ bh1,
                          const float* __restrict__ Wh2, const float* __restrict__ bh2,
                          float* __restrict__ out) {
    __shared__ float z[NG][128];
    int w = threadIdx.x >> 5;
    int lane = threadIdx.x & 31;

    float cnt = fmaxf(g_gcnt[w], 1.0f);
    z[w][lane]      = g_gsum[w * 64 + lane] / cnt;
    z[w][lane + 32] = g_gsum[w * 64 + lane + 32] / cnt;

    float s = bp[lane];
#pragma unroll
    for (int k = 0; k < 7; k++) s = fmaf(pk[w * 7 + k], Wp[lane * 7 + k], s);
    z[w][64 + lane] = fmaxf(s, 0.f);

    s = bc[lane];
#pragma unroll
    for (int k = 0; k < 4; k++) s = fmaf(ck[w * 4 + k], Wc[lane * 4 + k], s);
    z[w][96 + lane] = fmaxf(s, 0.f);
    __syncwarp();

    float a0 = bh1[lane], a1 = bh1[lane + 32];
#pragma unroll 4
    for (int k = 0; k < 128; k++) {
        float zv = z[w][k];
        a0 = fmaf(zv, Wh1[lane * 128 + k], a0);
        a1 = fmaf(zv, Wh1[(lane + 32) * 128 + k], a1);
    }
    a0 = fmaxf(a0, 0.f);
    a1 = fmaxf(a1, 0.f);
    float r = a0 * Wh2[lane] + a1 * Wh2[lane + 32];
#pragma unroll
    for (int off = 16; off > 0; off >>= 1) r += __shfl_down_sync(0xffffffffu, r, off);
    if (lane == 0) out[w] = r + bh2[0];
}

// ---------------- launch -----------------------------------------------------
extern "C" void kernel_launch(void* const* d_in, const int* in_sizes, int n_in,
                              void* d_out, int out_size) {
    const float* x    = (const float*)d_in[0];
    const float* pk   = (const float*)d_in[1];
    const float* ck   = (const float*)d_in[2];
    const float* Wl   = (const float*)d_in[3];
    const float* bl   = (const float*)d_in[4];
    const float* Wr   = (const float*)d_in[5];
    const float* Wp   = (const float*)d_in[6];
    const float* bp   = (const float*)d_in[7];
    const float* Wc   = (const float*)d_in[8];
    const float* bc   = (const float*)d_in[9];
    const float* Wh1  = (const float*)d_in[10];
    const float* bh1  = (const float*)d_in[11];
    const float* Wh2  = (const float*)d_in[12];
    const float* bh2  = (const float*)d_in[13];
    const int*   ei   = (const int*)d_in[14];
    const int*   batch= (const int*)d_in[15];
    float* out = (float*)d_out;

    // slots 1-3: zeroing (node_gemm stays in profiled slot 4)
    zero_agg_lo<<<1024, 256>>>();
    zero_agg_hi<<<1024, 256>>>();
    zero_small<<<1, 1024>>>();

    // slot 4: node GEMM (tf32 tensor cores)  <-- profiled
    int gemm_smem = 128 * 132 * 4;   // 67584 bytes
    cudaFuncSetAttribute(node_gemm, cudaFuncAttributeMaxDynamicSharedMemorySize, gemm_smem);
    node_gemm<<<(N_NODES + GEMM_BM - 1) / GEMM_BM, 256, gemm_smem>>>(x, Wl, Wr);

    // slot 5: edge scatter
    edge_scatter<<<(N_EDGES + 15) / 16, 256>>>(ei);

    // slot 6: combine + pool
    combine_pool<<<POOL_BLOCKS, 256>>>(bl, batch);

    // slot 7: final MLP
    final_mlp<<<1, 512>>>(pk, ck, Wp, bp, Wc, bc, Wh1, bh1, Wh2, bh2, out);

    (void)in_sizes; (void)n_in; (void)out_size;
}

// round 10
// speedup vs baseline: 2.2083x; 1.2386x over previous
#include <cuda_runtime.h>
#include <cuda_fp16.h>
#include <cuda_bf16.h>

#define N_NODES 100000
#define N_EDGES 1600000
#define IN_CH   128
#define NG      16

typedef unsigned long long ull;

// ---------------- scratch (device globals) ----------------------------------
__device__ __half g_yh  [N_NODES * 64];   // x @ W_l^T  (fp16)
__device__ float  g_xr  [N_NODES * 64];   // x @ W_r^T  (fp32)
__device__ __half g_aggh[N_NODES * 64];   // segment_sum of y over dst (fp16)
__device__ float  g_deg [N_NODES];
__device__ float  g_gsum[NG * 64];
__device__ float  g_gcnt[NG];

// ---------------- kernel (slot 1): zero agg (fp16) + deg ---------------------
__global__ void zero_agg() {
    int i = blockIdx.x * blockDim.x + threadIdx.x;
    int stride = gridDim.x * blockDim.x;
    uint4 z = make_uint4(0u, 0u, 0u, 0u);
    uint4* a4 = reinterpret_cast<uint4*>(g_aggh);
    for (int j = i; j < N_NODES * 8; j += stride) a4[j] = z;   // 12.8 MB
    for (int j = i; j < N_NODES; j += stride) g_deg[j] = 0.f;
}
// ---------------- kernel (slot 3): zero pool accumulators --------------------
__global__ void zero_small() {
    int i = threadIdx.x;
    if (i < NG * 64) g_gsum[i] = 0.f;
    if (i < NG) g_gcnt[i] = 0.f;
}

// ---------------- kernel (slot 2): node GEMM via tf32 mma.sync ---------------
// [y | xr] = x @ [W_l ; W_r]^T ; y stored fp16, xr fp32.
#define GEMM_BM 128
__device__ __forceinline__ unsigned f2tf32(float f) {
    unsigned u;
    asm("cvt.rna.tf32.f32 %0, %1;" : "=r"(u) : "f"(f));
    return u;
}
__global__ void __launch_bounds__(256, 2) node_gemm(const float* __restrict__ x,
                          const float* __restrict__ Wl,
                          const float* __restrict__ Wr) {
    extern __shared__ unsigned Wsm[];   // [128][132] tf32 bits; Wsm[n][k]

    int tid = threadIdx.x;
    for (int idx = tid; idx < 128 * 128; idx += 256) {
        int n = idx >> 7, k = idx & 127;
        float v = (n < 64) ? Wl[n * 128 + k] : Wr[(n - 64) * 128 + k];
        Wsm[n * 132 + k] = f2tf32(v);
    }
    __syncthreads();

    int w    = tid >> 5;
    int lane = tid & 31;
    int gid  = lane >> 2;
    int tig  = lane & 3;

    int nodeBase = blockIdx.x * GEMM_BM + w * 16;
    int r0 = nodeBase + gid;
    int r1 = r0 + 8;
    int r0c = min(r0, N_NODES - 1);
    int r1c = min(r1, N_NODES - 1);
    const float* xr0 = x + (size_t)r0c * 128;
    const float* xr1 = x + (size_t)r1c * 128;

    float acc[16][4];
#pragma unroll
    for (int nt = 0; nt < 16; nt++)
#pragma unroll
        for (int c = 0; c < 4; c++) acc[nt][c] = 0.f;

#pragma unroll
    for (int ks = 0; ks < 16; ks++) {
        int c0 = ks * 8 + tig;
        unsigned a0 = f2tf32(__ldg(xr0 + c0));
        unsigned a1 = f2tf32(__ldg(xr1 + c0));
        unsigned a2 = f2tf32(__ldg(xr0 + c0 + 4));
        unsigned a3 = f2tf32(__ldg(xr1 + c0 + 4));
#pragma unroll
        for (int nt = 0; nt < 16; nt++) {
            unsigned b0 = Wsm[(nt * 8 + gid) * 132 + ks * 8 + tig];
            unsigned b1 = Wsm[(nt * 8 + gid) * 132 + ks * 8 + tig + 4];
            asm("mma.sync.aligned.m16n8k8.row.col.f32.tf32.tf32.f32 "
                "{%0,%1,%2,%3}, {%4,%5,%6,%7}, {%8,%9}, {%0,%1,%2,%3};"
                : "+f"(acc[nt][0]), "+f"(acc[nt][1]), "+f"(acc[nt][2]), "+f"(acc[nt][3])
                : "r"(a0), "r"(a1), "r"(a2), "r"(a3), "r"(b0), "r"(b1));
        }
    }

#pragma unroll
    for (int nt = 0; nt < 16; nt++) {
        int j = nt * 8 + 2 * tig;          // 0..127, even
        if (j < 64) {
            __half2 lo = __floats2half2_rn(acc[nt][0], acc[nt][1]);
            __half2 hi = __floats2half2_rn(acc[nt][2], acc[nt][3]);
            if (r0 < N_NODES) *reinterpret_cast<__half2*>(&g_yh[(size_t)r0 * 64 + j]) = lo;
            if (r1 < N_NODES) *reinterpret_cast<__half2*>(&g_yh[(size_t)r1 * 64 + j]) = hi;
        } else {
            float2 lo = make_float2(acc[nt][0], acc[nt][1]);
            float2 hi = make_float2(acc[nt][2], acc[nt][3]);
            if (r0 < N_NODES) *reinterpret_cast<float2*>(&g_xr[(size_t)r0 * 64 + j - 64]) = lo;
            if (r1 < N_NODES) *reinterpret_cast<float2*>(&g_xr[(size_t)r1 * 64 + j - 64]) = hi;
        }
    }
}

// ---------------- kernel (slot 4): edge scatter, fp16 v4.f16x2 reds ----------
// 8 lanes/edge; each lane moves 8 halves (16B).
__global__ void edge_scatter(const int* __restrict__ ei) {
    int tid = threadIdx.x;
    int e = blockIdx.x * 32 + (tid >> 3);
    int t = tid & 7;
    if (e >= N_EDGES) return;
    int src = __ldg(&ei[e]);
    int dst = __ldg(&ei[N_EDGES + e]);

    const uint4* ysrc = reinterpret_cast<const uint4*>(g_yh + (size_t)src * 64);
    uint4 v = __ldg(ysrc + t);
    __half* dptr = g_aggh + (size_t)dst * 64 + t * 8;
    asm volatile("red.global.add.noftz.v4.f16x2 [%0], {%1, %2, %3, %4};"
                 :: "l"(dptr), "r"(v.x), "r"(v.y), "r"(v.z), "r"(v.w)
                 : "memory");
    if (t == 0) {
        float* dp = g_deg + dst;
        asm volatile("red.global.add.f32 [%0], %1;" :: "l"(dp), "f"(1.0f) : "memory");
    }
}

// ---------------- kernel (slot 5): combine + per-graph pool ------------------
// lane handles channels 2*lane, 2*lane+1 (half2-friendly).
#define POOL_BLOCKS 592
#define POOL_WARPS  (POOL_BLOCKS * 8)
#define POOL_CHUNK  ((N_NODES + POOL_WARPS - 1) / POOL_WARPS)
__global__ void combine_pool(const float* __restrict__ bl,
                             const int* __restrict__ batch) {
    int wid = (blockIdx.x * blockDim.x + threadIdx.x) >> 5;
    int lane = threadIdx.x & 31;
    int start = wid * POOL_CHUNK;
    if (start >= N_NODES) return;
    int end = min(start + POOL_CHUNK, N_NODES);

    float bl0 = bl[2 * lane], bl1 = bl[2 * lane + 1];
    float acc0 = 0.f, acc1 = 0.f, cnt = 0.f;
    int cur = batch[start];

    for (int n = start; n < end; n++) {
        int b = batch[n];
        if (b != cur) {
            atomicAdd(&g_gsum[cur * 64 + 2 * lane], acc0);
            atomicAdd(&g_gsum[cur * 64 + 2 * lane + 1], acc1);
            if (lane == 0) atomicAdd(&g_gcnt[cur], cnt);
            acc0 = acc1 = cnt = 0.f;
            cur = b;
        }
        float inv = 1.0f / fmaxf(g_deg[n], 1.0f);
        __half2 ah = *reinterpret_cast<const __half2*>(&g_aggh[(size_t)n * 64 + 2 * lane]);
        float2 av = __half22float2(ah);
        float2 xv = *reinterpret_cast<const float2*>(&g_xr[(size_t)n * 64 + 2 * lane]);
        float h0 = fmaxf(fmaf(av.x, inv, xv.x + bl0), 0.f);
        float h1 = fmaxf(fmaf(av.y, inv, xv.y + bl1), 0.f);
        acc0 += h0; acc1 += h1; cnt += 1.f;
    }
    atomicAdd(&g_gsum[cur * 64 + 2 * lane], acc0);
    atomicAdd(&g_gsum[cur * 64 + 2 * lane + 1], acc1);
    if (lane == 0) atomicAdd(&g_gcnt[cur], cnt);
}

// ---------------- kernel (slot 6): final MLP ---------------------------------
__global__ void final_mlp(const float* __restrict__ pk, const float* __restrict__ ck,
                          const float* __restrict__ Wp, const float* __restrict__ bp,
                          const float* __restrict__ Wc, const float* __restrict__ bc,
                          const float* __restrict__ Wh1, const float* __restrict__ bh1,
                          const float* __restrict__ Wh2, const float* __restrict__ bh2,
                          float* __restrict__ out) {
    __shared__ float z[NG][128];
    int w = threadIdx.x >> 5;
    int lane = threadIdx.x & 31;

    float cnt = fmaxf(g_gcnt[w], 1.0f);
    z[w][lane]      = g_gsum[w * 64 + lane] / cnt;
    z[w][lane + 32] = g_gsum[w * 64 + lane + 32] / cnt;

    float s = bp[lane];
#pragma unroll
    for (int k = 0; k < 7; k++) s = fmaf(pk[w * 7 + k], Wp[lane * 7 + k], s);
    z[w][64 + lane] = fmaxf(s, 0.f);

    s = bc[lane];
#pragma unroll
    for (int k = 0; k < 4; k++) s = fmaf(ck[w * 4 + k], Wc[lane * 4 + k], s);
    z[w][96 + lane] = fmaxf(s, 0.f);
    __syncwarp();

    float a0 = bh1[lane], a1 = bh1[lane + 32];
#pragma unroll 4
    for (int k = 0; k < 128; k++) {
        float zv = z[w][k];
        a0 = fmaf(zv, Wh1[lane * 128 + k], a0);
        a1 = fmaf(zv, Wh1[(lane + 32) * 128 + k], a1);
    }
    a0 = fmaxf(a0, 0.f);
    a1 = fmaxf(a1, 0.f);
    float r = a0 * Wh2[lane] + a1 * Wh2[lane + 32];
#pragma unroll
    for (int off = 16; off > 0; off >>= 1) r += __shfl_down_sync(0xffffffffu, r, off);
    if (lane == 0) out[w] = r + bh2[0];
}

// ---------------- launch -----------------------------------------------------
extern "C" void kernel_launch(void* const* d_in, const int* in_sizes, int n_in,
                              void* d_out, int out_size) {
    const float* x    = (const float*)d_in[0];
    const float* pk   = (const float*)d_in[1];
    const float* ck   = (const float*)d_in[2];
    const float* Wl   = (const float*)d_in[3];
    const float* bl   = (const float*)d_in[4];
    const float* Wr   = (const float*)d_in[5];
    const float* Wp   = (const float*)d_in[6];
    const float* bp   = (const float*)d_in[7];
    const float* Wc   = (const float*)d_in[8];
    const float* bc   = (const float*)d_in[9];
    const float* Wh1  = (const float*)d_in[10];
    const float* bh1  = (const float*)d_in[11];
    const float* Wh2  = (const float*)d_in[12];
    const float* bh2  = (const float*)d_in[13];
    const int*   ei   = (const int*)d_in[14];
    const int*   batch= (const int*)d_in[15];
    float* out = (float*)d_out;

    // slot 1: zero agg (fp16) + deg
    zero_agg<<<1024, 256>>>();

    // slot 2: node GEMM (tf32 tensor cores)
    int gemm_smem = 128 * 132 * 4;
    cudaFuncSetAttribute(node_gemm, cudaFuncAttributeMaxDynamicSharedMemorySize, gemm_smem);
    node_gemm<<<(N_NODES + GEMM_BM - 1) / GEMM_BM, 256, gemm_smem>>>(x, Wl, Wr);

    // slot 3: tiny zero
    zero_small<<<1, 1024>>>();

    // slot 4: edge scatter (fp16)  <-- profiled
    edge_scatter<<<(N_EDGES + 31) / 32, 256>>>(ei);

    // slot 5: combine + pool
    combine_pool<<<POOL_BLOCKS, 256>>>(bl, batch);

    // slot 6: final MLP
    final_mlp<<<1, 512>>>(pk, ck, Wp, bp, Wc, bc, Wh1, bh1, Wh2, bh2, out);

    (void)in_sizes; (void)n_in; (void)out_size;
}